// round 4
// baseline (speedup 1.0000x reference)
#include <cuda_runtime.h>
#include <cstdint>

// Problem constants (fixed shapes for this problem)
#define MAX_N 50000
#define MAX_E 800000
#define F_IN  128
#define F_HID 128
#define F_OUT 64

// Scratch (device globals; no allocation allowed in kernel_launch)
__device__ float g_h1 [MAX_N * F_HID];   // layer1 linear output
__device__ float g_agg[MAX_N * F_HID];   // layer1 aggregation buffer (pre-activation)
__device__ float g_h3 [MAX_N * F_OUT];   // layer2 linear output
__device__ float g_dinv[MAX_N];
__device__ int   g_deg [MAX_N];

// ---------------------------------------------------------------------------
// degree kernels
// ---------------------------------------------------------------------------
__global__ void k_deg_zero(int n) {
    int i = blockIdx.x * blockDim.x + threadIdx.x;
    if (i < n) g_deg[i] = 0;
}

__global__ void k_deg_count(const int* __restrict__ ei, int E) {
    int e = blockIdx.x * blockDim.x + threadIdx.x;
    if (e < E) atomicAdd(&g_deg[ei[E + e]], 1);   // dst = ei[E + e]
}

__global__ void k_dinv(int n) {
    int i = blockIdx.x * blockDim.x + threadIdx.x;
    if (i < n) g_dinv[i] = rsqrtf((float)g_deg[i] + 1.0f);  // +1 self loop
}

// ---------------------------------------------------------------------------
// Tiled SGEMM: H = act(A)[M,128] @ W[128,BN]; also writes AGG = H * dinv(row)^2
// BM=128, BK=16, TM=8; double-buffered smem, conflict-free A-tile stores.
// If FUSE: act(a) = relu(a + bias[k]) applied while loading the A tile.
// grid.x = ceil(M/128), 256 threads.
// ---------------------------------------------------------------------------
template <int BN, int TN, bool FUSE>
__global__ void __launch_bounds__(256, 2)
k_gemm_fused(const float* __restrict__ A,
             const float* __restrict__ W,
             const float* __restrict__ bias,   // layer-1 bias if FUSE
             float* __restrict__ H,
             float* __restrict__ AGG,
             const float* __restrict__ dinv,
             int M) {
    constexpr int BM = 128, BK = 16, TM = 8;
    constexpr int TX = BN / TN;               // threads along N
    static_assert(TX * (BM / TM) == 256, "block must be 256 threads");
    constexpr int BV = BN / 4;                // float4 per W tile row
    constexpr int NLB = (BK * BV) / 256;      // W tile float4 loads per thread
    constexpr int NK = 128 / BK;              // 8 k-tiles

    __shared__ float As[2][BK][BM];
    __shared__ float Bs[2][BK][BN];

    const int tid  = threadIdx.x;
    const int ty   = tid / TX;
    const int tx   = tid % TX;
    const int row0 = blockIdx.x * BM;

    // A-tile mapping: conflict-free STS (warp lanes cover 32 distinct rows)
    const int ar  = tid & 127;                // row in tile
    const int ac0 = (tid >> 7) * 4;           // col group: 0 or 4 (second ld: +8)
    const int agrow = row0 + ar;
    const bool arow_ok = (agrow < M);
    const float* Arow = A + (size_t)agrow * 128;

    float acc[TM][TN];
#pragma unroll
    for (int m = 0; m < TM; m++)
#pragma unroll
        for (int n = 0; n < TN; n++) acc[m][n] = 0.0f;

    float4 pa[2];                             // A prefetch regs
    float4 pb[NLB];                           // W prefetch regs

    auto load_gmem = [&](int k0) {
#pragma unroll
        for (int i = 0; i < 2; i++) {
            int c = ac0 + i * 8;
            float4 v = make_float4(0.f, 0.f, 0.f, 0.f);
            if (arow_ok) {
                v = *(const float4*)(Arow + k0 + c);
                if (FUSE) {
                    float4 bb = *(const float4*)(bias + k0 + c);
                    v.x = fmaxf(v.x + bb.x, 0.0f);
                    v.y = fmaxf(v.y + bb.y, 0.0f);
                    v.z = fmaxf(v.z + bb.z, 0.0f);
                    v.w = fmaxf(v.w + bb.w, 0.0f);
                }
            }
            pa[i] = v;
        }
#pragma unroll
        for (int i = 0; i < NLB; i++) {
            int l = tid + i * 256;
            int r = l / BV;
            int c = (l % BV) * 4;
            pb[i] = *(const float4*)(W + (size_t)(k0 + r) * BN + c);
        }
    };

    auto store_smem = [&](int buf) {
#pragma unroll
        for (int i = 0; i < 2; i++) {
            int c = ac0 + i * 8;
            As[buf][c + 0][ar] = pa[i].x;
            As[buf][c + 1][ar] = pa[i].y;
            As[buf][c + 2][ar] = pa[i].z;
            As[buf][c + 3][ar] = pa[i].w;
        }
#pragma unroll
        for (int i = 0; i < NLB; i++) {
            int l = tid + i * 256;
            int r = l / BV;
            int c = (l % BV) * 4;
            *(float4*)(&Bs[buf][r][c]) = pb[i];
        }
    };

    auto compute = [&](int buf) {
#pragma unroll
        for (int k = 0; k < BK; k++) {
            float am[TM], bn[TN];
#pragma unroll
            for (int m = 0; m < TM; m++) am[m] = As[buf][k][ty * TM + m];
#pragma unroll
            for (int n = 0; n < TN; n++) bn[n] = Bs[buf][k][tx * TN + n];
#pragma unroll
            for (int m = 0; m < TM; m++)
#pragma unroll
                for (int n = 0; n < TN; n++)
                    acc[m][n] = fmaf(am[m], bn[n], acc[m][n]);
        }
    };

    load_gmem(0);
    store_smem(0);
    __syncthreads();
#pragma unroll
    for (int it = 0; it < NK - 1; it++) {
        load_gmem((it + 1) * BK);
        compute(it & 1);
        store_smem((it + 1) & 1);
        __syncthreads();
    }
    compute((NK - 1) & 1);

    // Epilogue: write H and AGG = H * dinv^2 (self-loop term)
#pragma unroll
    for (int m = 0; m < TM; m++) {
        int grow = row0 + ty * TM + m;
        if (grow < M) {
            float d  = dinv[grow];
            float dd = d * d;
#pragma unroll
            for (int n = 0; n < TN; n += 4) {
                float4 v;
                v.x = acc[m][n + 0];
                v.y = acc[m][n + 1];
                v.z = acc[m][n + 2];
                v.w = acc[m][n + 3];
                int col = tx * TN + n;
                *(float4*)(H + (size_t)grow * BN + col) = v;
                float4 w = make_float4(v.x * dd, v.y * dd, v.z * dd, v.w * dd);
                *(float4*)(AGG + (size_t)grow * BN + col) = w;
            }
        }
    }
}

// ---------------------------------------------------------------------------
// Edge scatter: agg[dst] += h[src] * dinv[src]*dinv[dst]
// F/4 lanes per edge, vector float4 RED atomics.
// ---------------------------------------------------------------------------
template <int F>
__global__ void k_scatter(const int* __restrict__ ei,
                          const float* __restrict__ h,
                          float* __restrict__ agg,
                          const float* __restrict__ dinv,
                          int E) {
    constexpr int LPE = F / 4;                // lanes per edge (32 or 16)
    int gt = blockIdx.x * blockDim.x + threadIdx.x;
    int e  = gt / LPE;
    int li = gt % LPE;
    if (e >= E) return;

    int src = __ldg(&ei[e]);
    int dst = __ldg(&ei[E + e]);
    float norm = dinv[src] * dinv[dst];

    float4 v = *(const float4*)(h + (size_t)src * F + li * 4);
    float* p = agg + (size_t)dst * F + li * 4;
    asm volatile("red.global.add.v4.f32 [%0], {%1, %2, %3, %4};"
                 :: "l"(p),
                    "f"(v.x * norm), "f"(v.y * norm),
                    "f"(v.z * norm), "f"(v.w * norm)
                 : "memory");
}

// ---------------------------------------------------------------------------
// out = relu(agg + b), vectorized float4 (final layer only)
// ---------------------------------------------------------------------------
template <int F>
__global__ void k_bias_relu(const float* __restrict__ agg,
                            const float* __restrict__ b,
                            float* __restrict__ out,
                            int M) {
    int i = blockIdx.x * blockDim.x + threadIdx.x;    // over M*F/4 float4
    int total = M * (F / 4);
    if (i >= total) return;
    int col4 = (i % (F / 4)) * 4;
    float4 v  = ((const float4*)agg)[i];
    float4 bb = *(const float4*)(b + col4);
    v.x = fmaxf(v.x + bb.x, 0.0f);
    v.y = fmaxf(v.y + bb.y, 0.0f);
    v.z = fmaxf(v.z + bb.z, 0.0f);
    v.w = fmaxf(v.w + bb.w, 0.0f);
    ((float4*)out)[i] = v;
}

// ---------------------------------------------------------------------------
// launch
// ---------------------------------------------------------------------------
extern "C" void kernel_launch(void* const* d_in, const int* in_sizes, int n_in,
                              void* d_out, int out_size) {
    const float* x  = (const float*)d_in[0];
    const int*   ei = (const int*)  d_in[1];
    const float* W1 = (const float*)d_in[2];
    const float* b1 = (const float*)d_in[3];
    const float* W2 = (const float*)d_in[4];
    const float* b2 = (const float*)d_in[5];
    float* out = (float*)d_out;

    const int N = in_sizes[0] / F_IN;
    const int E = in_sizes[1] / 2;

    float *p_h1, *p_agg, *p_h3, *p_dinv;
    cudaGetSymbolAddress((void**)&p_h1,   g_h1);
    cudaGetSymbolAddress((void**)&p_agg,  g_agg);
    cudaGetSymbolAddress((void**)&p_h3,   g_h3);
    cudaGetSymbolAddress((void**)&p_dinv, g_dinv);

    const int T = 256;

    // degrees -> dinv
    k_deg_zero <<<(N + T - 1) / T, T>>>(N);
    k_deg_count<<<(E + T - 1) / T, T>>>(ei, E);
    k_dinv     <<<(N + T - 1) / T, T>>>(N);

    // ---- layer 1 ----
    k_gemm_fused<F_HID, 8, false><<<(N + 127) / 128, 256>>>(x, W1, nullptr,
                                                            p_h1, p_agg, p_dinv, N);
    {
        long long threads = (long long)E * (F_HID / 4);
        k_scatter<F_HID><<<(int)((threads + T - 1) / T), T>>>(ei, p_h1, p_agg, p_dinv, E);
    }

    // ---- layer 2 ----  (relu(agg + b1) fused into the A-tile load)
    k_gemm_fused<F_OUT, 4, true><<<(N + 127) / 128, 256>>>(p_agg, W2, b1,
                                                           p_h3, out, p_dinv, N);
    {
        long long threads = (long long)E * (F_OUT / 4);
        k_scatter<F_OUT><<<(int)((threads + T - 1) / T), T>>>(ei, p_h3, out, p_dinv, E);
    }
    k_bias_relu<F_OUT><<<(N * (F_OUT / 4) + T - 1) / T, T>>>(out, b2, out, N);
}

// round 7
// speedup vs baseline: 1.1976x; 1.1976x over previous
#include <cuda_runtime.h>
#include <cstdint>

// Problem constants (fixed shapes for this problem)
#define MAX_N 50000
#define MAX_E 800000
#define F_IN  128
#define F_HID 128
#define F_OUT 64

// Scratch (device globals; no allocation allowed in kernel_launch)
__device__ float g_h1 [MAX_N * F_HID];   // layer1 linear output
__device__ float g_agg[MAX_N * F_HID];   // layer1 aggregation buffer (pre-activation)
__device__ float g_h3 [MAX_N * F_OUT];   // layer2 linear output
__device__ float g_dinv[MAX_N];
__device__ int   g_deg [MAX_N];

// ---------------------------------------------------------------------------
// packed f32x2 helpers (Blackwell FFMA2 path — ptxas never emits it from C++)
// ---------------------------------------------------------------------------
__device__ __forceinline__ unsigned long long ffma2(unsigned long long a,
                                                    unsigned long long b,
                                                    unsigned long long c) {
    unsigned long long d;
    asm("fma.rn.f32x2 %0, %1, %2, %3;" : "=l"(d) : "l"(a), "l"(b), "l"(c));
    return d;
}
__device__ __forceinline__ unsigned long long dup2(float x) {
    unsigned long long d;
    asm("mov.b64 %0, {%1, %1};" : "=l"(d) : "f"(x));
    return d;
}
__device__ __forceinline__ float2 unpack2(unsigned long long v) {
    float2 r;
    r.x = __uint_as_float((unsigned)(v & 0xffffffffull));
    r.y = __uint_as_float((unsigned)(v >> 32));
    return r;
}

// ---------------------------------------------------------------------------
// degree kernels
// ---------------------------------------------------------------------------
__global__ void k_deg_zero(int n) {
    int i = blockIdx.x * blockDim.x + threadIdx.x;
    if (i < n) g_deg[i] = 0;
}

__global__ void k_deg_count(const int* __restrict__ ei, int E) {
    int e = blockIdx.x * blockDim.x + threadIdx.x;
    if (e < E) atomicAdd(&g_deg[ei[E + e]], 1);   // dst = ei[E + e]
}

__global__ void k_dinv(int n) {
    int i = blockIdx.x * blockDim.x + threadIdx.x;
    if (i < n) g_dinv[i] = rsqrtf((float)g_deg[i] + 1.0f);  // +1 self loop
}

// ---------------------------------------------------------------------------
// Tiled SGEMM with packed FFMA2: H = act(A)[M,128] @ W[128,BN];
// also writes AGG = H * dinv(row)^2 (self-loop term).
// BM=128, BK=16, TM=8; single-buffered smem (R2 structure),
// conflict-free A-tile STS. If FUSE: act(a) = relu(a + bias[k]) on A-tile load.
// grid.x = ceil(M/128), 256 threads.
// ---------------------------------------------------------------------------
template <int BN, int TN, bool FUSE>
__global__ void k_gemm_fused(const float* __restrict__ A,
                             const float* __restrict__ W,
                             const float* __restrict__ bias,
                             float* __restrict__ H,
                             float* __restrict__ AGG,
                             const float* __restrict__ dinv,
                             int M) {
    constexpr int BM = 128, BK = 16, TM = 8;
    constexpr int TX  = BN / TN;              // threads along N
    constexpr int TNP = TN / 2;               // packed f32x2 accs along N
    static_assert(TX * (BM / TM) == 256, "block must be 256 threads");
    constexpr int BV  = BN / 4;               // float4 per W tile row
    constexpr int NLB = (BK * BV) / 256;      // W tile float4 loads per thread

    __shared__ float As[BK][BM];              // transposed A tile
    __shared__ float Bs[BK][BN];

    const int tid  = threadIdx.x;
    const int ty   = tid / TX;
    const int tx   = tid % TX;
    const int row0 = blockIdx.x * BM;

    // A-tile mapping: conflict-free STS (warp lanes cover 32 distinct rows)
    const int ar  = tid & 127;                // row in tile
    const int ac0 = (tid >> 7) * 4;           // col group: 0 or 4 (2nd ld: +8)
    const int agrow = row0 + ar;
    const bool arow_ok = (agrow < M);
    const float* Arow = A + (size_t)agrow * 128;

    unsigned long long acc2[TM][TNP];
#pragma unroll
    for (int m = 0; m < TM; m++)
#pragma unroll
        for (int j = 0; j < TNP; j++) acc2[m][j] = 0ull;

    for (int k0 = 0; k0 < 128; k0 += BK) {
        // ---- global loads into regs (issue before barrier for overlap) ----
        float4 pa[2];
#pragma unroll
        for (int i = 0; i < 2; i++) {
            int c = ac0 + i * 8;
            float4 v = make_float4(0.f, 0.f, 0.f, 0.f);
            if (arow_ok) {
                v = *(const float4*)(Arow + k0 + c);
                if (FUSE) {
                    float4 bb = *(const float4*)(bias + k0 + c);
                    v.x = fmaxf(v.x + bb.x, 0.0f);
                    v.y = fmaxf(v.y + bb.y, 0.0f);
                    v.z = fmaxf(v.z + bb.z, 0.0f);
                    v.w = fmaxf(v.w + bb.w, 0.0f);
                }
            }
            pa[i] = v;
        }
        float4 pb[NLB];
#pragma unroll
        for (int i = 0; i < NLB; i++) {
            int l = tid + i * 256;
            int r = l / BV;
            int c = (l % BV) * 4;
            pb[i] = *(const float4*)(W + (size_t)(k0 + r) * BN + c);
        }

        __syncthreads();   // previous tile's compute done reading smem
        // ---- store smem ----
#pragma unroll
        for (int i = 0; i < 2; i++) {
            int c = ac0 + i * 8;
            As[c + 0][ar] = pa[i].x;
            As[c + 1][ar] = pa[i].y;
            As[c + 2][ar] = pa[i].z;
            As[c + 3][ar] = pa[i].w;
        }
#pragma unroll
        for (int i = 0; i < NLB; i++) {
            int l = tid + i * 256;
            int r = l / BV;
            int c = (l % BV) * 4;
            *(float4*)(&Bs[r][c]) = pb[i];
        }
        __syncthreads();

        // ---- compute (packed f32x2) ----
#pragma unroll
        for (int k = 0; k < BK; k++) {
            float4 a0 = *(const float4*)(&As[k][ty * TM]);
            float4 a1 = *(const float4*)(&As[k][ty * TM + 4]);
            unsigned long long bn2[TNP];
            {
                const ulonglong2* bp = (const ulonglong2*)(&Bs[k][tx * TN]);
                ulonglong2 t0 = bp[0];
                bn2[0] = t0.x; bn2[1] = t0.y;
                if (TNP == 4) {
                    ulonglong2 t1 = bp[1];
                    bn2[2] = t1.x; bn2[3] = t1.y;
                }
            }
            float am[TM] = {a0.x, a0.y, a0.z, a0.w, a1.x, a1.y, a1.z, a1.w};
#pragma unroll
            for (int m = 0; m < TM; m++) {
                unsigned long long a2 = dup2(am[m]);
#pragma unroll
                for (int j = 0; j < TNP; j++)
                    acc2[m][j] = ffma2(a2, bn2[j], acc2[m][j]);
            }
        }
    }

    // Epilogue: write H and AGG = H * dinv^2 (self-loop term)
#pragma unroll
    for (int m = 0; m < TM; m++) {
        int grow = row0 + ty * TM + m;
        if (grow < M) {
            float d  = dinv[grow];
            float dd = d * d;
#pragma unroll
            for (int j = 0; j < TNP; j += 2) {
                float2 p0 = unpack2(acc2[m][j]);
                float2 p1 = unpack2(acc2[m][j + 1]);
                float4 v = make_float4(p0.x, p0.y, p1.x, p1.y);
                int col = tx * TN + j * 2;
                *(float4*)(H + (size_t)grow * BN + col) = v;
                float4 w = make_float4(v.x * dd, v.y * dd, v.z * dd, v.w * dd);
                *(float4*)(AGG + (size_t)grow * BN + col) = w;
            }
        }
    }
}

// ---------------------------------------------------------------------------
// Edge scatter: agg[dst] += h[src] * dinv[src]*dinv[dst]
// F/4 lanes per edge, vector float4 RED atomics.
// ---------------------------------------------------------------------------
template <int F>
__global__ void k_scatter(const int* __restrict__ ei,
                          const float* __restrict__ h,
                          float* __restrict__ agg,
                          const float* __restrict__ dinv,
                          int E) {
    constexpr int LPE = F / 4;                // lanes per edge (32 or 16)
    int gt = blockIdx.x * blockDim.x + threadIdx.x;
    int e  = gt / LPE;
    int li = gt % LPE;
    if (e >= E) return;

    int src = __ldg(&ei[e]);
    int dst = __ldg(&ei[E + e]);
    float norm = dinv[src] * dinv[dst];

    float4 v = *(const float4*)(h + (size_t)src * F + li * 4);
    float* p = agg + (size_t)dst * F + li * 4;
    asm volatile("red.global.add.v4.f32 [%0], {%1, %2, %3, %4};"
                 :: "l"(p),
                    "f"(v.x * norm), "f"(v.y * norm),
                    "f"(v.z * norm), "f"(v.w * norm)
                 : "memory");
}

// ---------------------------------------------------------------------------
// out = relu(agg + b), vectorized float4 (final layer only)
// ---------------------------------------------------------------------------
template <int F>
__global__ void k_bias_relu(const float* __restrict__ agg,
                            const float* __restrict__ b,
                            float* __restrict__ out,
                            int M) {
    int i = blockIdx.x * blockDim.x + threadIdx.x;    // over M*F/4 float4
    int total = M * (F / 4);
    if (i >= total) return;
    int col4 = (i % (F / 4)) * 4;
    float4 v  = ((const float4*)agg)[i];
    float4 bb = *(const float4*)(b + col4);
    v.x = fmaxf(v.x + bb.x, 0.0f);
    v.y = fmaxf(v.y + bb.y, 0.0f);
    v.z = fmaxf(v.z + bb.z, 0.0f);
    v.w = fmaxf(v.w + bb.w, 0.0f);
    ((float4*)out)[i] = v;
}

// ---------------------------------------------------------------------------
// launch
// ---------------------------------------------------------------------------
extern "C" void kernel_launch(void* const* d_in, const int* in_sizes, int n_in,
                              void* d_out, int out_size) {
    const float* x  = (const float*)d_in[0];
    const int*   ei = (const int*)  d_in[1];
    const float* W1 = (const float*)d_in[2];
    const float* b1 = (const float*)d_in[3];
    const float* W2 = (const float*)d_in[4];
    const float* b2 = (const float*)d_in[5];
    float* out = (float*)d_out;

    const int N = in_sizes[0] / F_IN;
    const int E = in_sizes[1] / 2;

    float *p_h1, *p_agg, *p_h3, *p_dinv;
    cudaGetSymbolAddress((void**)&p_h1,   g_h1);
    cudaGetSymbolAddress((void**)&p_agg,  g_agg);
    cudaGetSymbolAddress((void**)&p_h3,   g_h3);
    cudaGetSymbolAddress((void**)&p_dinv, g_dinv);

    const int T = 256;

    // degrees -> dinv
    k_deg_zero <<<(N + T - 1) / T, T>>>(N);
    k_deg_count<<<(E + T - 1) / T, T>>>(ei, E);
    k_dinv     <<<(N + T - 1) / T, T>>>(N);

    // ---- layer 1 ----
    k_gemm_fused<F_HID, 8, false><<<(N + 127) / 128, 256>>>(x, W1, nullptr,
                                                            p_h1, p_agg, p_dinv, N);
    {
        long long threads = (long long)E * (F_HID / 4);
        k_scatter<F_HID><<<(int)((threads + T - 1) / T), T>>>(ei, p_h1, p_agg, p_dinv, E);
    }

    // ---- layer 2 ----  (relu(agg + b1) fused into the A-tile load)
    k_gemm_fused<F_OUT, 4, true><<<(N + 127) / 128, 256>>>(p_agg, W2, b1,
                                                           p_h3, out, p_dinv, N);
    {
        long long threads = (long long)E * (F_OUT / 4);
        k_scatter<F_OUT><<<(int)((threads + T - 1) / T), T>>>(ei, p_h3, out, p_dinv, E);
    }
    k_bias_relu<F_OUT><<<(N * (F_OUT / 4) + T - 1) / T, T>>>(out, b2, out, N);
}

// round 10
// speedup vs baseline: 1.6742x; 1.3980x over previous
#include <cuda_runtime.h>
#include <cstdint>

// Problem constants (fixed shapes for this problem)
#define MAX_N 50000
#define MAX_E 800000
#define F_IN  128
#define F_HID 128
#define F_OUT 64

// Scratch (device globals; no allocation allowed in kernel_launch)
__device__ float g_h1 [MAX_N * F_HID];   // layer1 linear output
__device__ float g_agg[MAX_N * F_HID];   // layer1 aggregated (pre-activation)
__device__ float g_h3 [MAX_N * F_OUT];   // layer2 linear output
__device__ float g_dinv[MAX_N];
__device__ int   g_deg [MAX_N];
// CSR (edges sorted by dst)
__device__ int   g_rowptr[MAX_N + 1];
__device__ int   g_cursor[MAX_N];
__device__ int   g_srcs  [MAX_E];
__device__ float g_normv [MAX_E];
__device__ int   g_bsum  [64];

// ---------------------------------------------------------------------------
// packed f32x2 helpers (Blackwell FFMA2 path — ptxas never emits it from C++)
// ---------------------------------------------------------------------------
__device__ __forceinline__ unsigned long long ffma2(unsigned long long a,
                                                    unsigned long long b,
                                                    unsigned long long c) {
    unsigned long long d;
    asm("fma.rn.f32x2 %0, %1, %2, %3;" : "=l"(d) : "l"(a), "l"(b), "l"(c));
    return d;
}
__device__ __forceinline__ unsigned long long dup2(float x) {
    unsigned long long d;
    asm("mov.b64 %0, {%1, %1};" : "=l"(d) : "f"(x));
    return d;
}
__device__ __forceinline__ float2 unpack2(unsigned long long v) {
    float2 r;
    r.x = __uint_as_float((unsigned)(v & 0xffffffffull));
    r.y = __uint_as_float((unsigned)(v >> 32));
    return r;
}

// ---------------------------------------------------------------------------
// degree / dinv
// ---------------------------------------------------------------------------
__global__ void k_deg_zero(int n) {
    int i = blockIdx.x * blockDim.x + threadIdx.x;
    if (i < n) g_deg[i] = 0;
}
__global__ void k_deg_count(const int* __restrict__ ei, int E) {
    int e = blockIdx.x * blockDim.x + threadIdx.x;
    if (e < E) atomicAdd(&g_deg[ei[E + e]], 1);   // dst = ei[E + e]
}
__global__ void k_dinv(int n) {
    int i = blockIdx.x * blockDim.x + threadIdx.x;
    if (i < n) g_dinv[i] = rsqrtf((float)g_deg[i] + 1.0f);  // +1 self loop
}

// ---------------------------------------------------------------------------
// 3-kernel exclusive scan of g_deg -> g_rowptr (tiles of 1024)
// ---------------------------------------------------------------------------
__global__ void k_scan_local(int n) {
    int i = blockIdx.x * 1024 + threadIdx.x;
    int v = (i < n) ? g_deg[i] : 0;
    int lane = threadIdx.x & 31, wid = threadIdx.x >> 5;
    int x = v;
#pragma unroll
    for (int o = 1; o < 32; o <<= 1) {
        int t = __shfl_up_sync(0xffffffffu, x, o);
        if (lane >= o) x += t;
    }
    __shared__ int wsum[32];
    if (lane == 31) wsum[wid] = x;
    __syncthreads();
    if (wid == 0) {
        int y = wsum[lane];
#pragma unroll
        for (int o = 1; o < 32; o <<= 1) {
            int t = __shfl_up_sync(0xffffffffu, y, o);
            if (lane >= o) y += t;
        }
        wsum[lane] = y;
    }
    __syncthreads();
    int incl = x + (wid > 0 ? wsum[wid - 1] : 0);
    if (i < n) g_rowptr[i] = incl - v;                  // tile-local exclusive
    if (threadIdx.x == 1023) g_bsum[blockIdx.x] = incl; // tile total
}
__global__ void k_scan_bsums(int nb) {
    if (threadIdx.x == 0) {
        int run = 0;
        for (int b = 0; b < nb; b++) { int t = g_bsum[b]; g_bsum[b] = run; run += t; }
    }
}
__global__ void k_scan_add(int n, int E) {
    int i = blockIdx.x * 1024 + threadIdx.x;
    if (i < n) {
        int rp = g_rowptr[i] + g_bsum[blockIdx.x];
        g_rowptr[i] = rp;
        g_cursor[i] = rp;
    }
    if (i == 0) g_rowptr[n] = E;
}

// ---------------------------------------------------------------------------
// fill CSR: scatter edges into dst-sorted order; precompute per-edge norm
// ---------------------------------------------------------------------------
__global__ void k_fill(const int* __restrict__ ei, int E) {
    int e = blockIdx.x * blockDim.x + threadIdx.x;
    if (e >= E) return;
    int src = ei[e];
    int dst = ei[E + e];
    int pos = atomicAdd(&g_cursor[dst], 1);
    g_srcs[pos]  = src;
    g_normv[pos] = g_dinv[src] * g_dinv[dst];
}

// ---------------------------------------------------------------------------
// CSR gather: out[i] = sum_{e in row i} h[src_e]*norm_e + h[i]*dinv[i]^2
// One warp per node. FINAL: out = relu(out + bias).
// ---------------------------------------------------------------------------
template <int F, bool FINAL>
__global__ void k_gather(const float* __restrict__ h,
                         const float* __restrict__ bias,
                         float* __restrict__ out, int N) {
    int warp = (blockIdx.x * blockDim.x + threadIdx.x) >> 5;
    int lane = threadIdx.x & 31;
    if (warp >= N) return;
    int beg = g_rowptr[warp];
    int end = g_rowptr[warp + 1];
    float d = g_dinv[warp];
    float dd = d * d;

    if (F == 128) {
        const float4* hr = (const float4*)(h + (size_t)warp * F) + lane;
        float4 hv = *hr;
        float4 acc = make_float4(hv.x * dd, hv.y * dd, hv.z * dd, hv.w * dd);
        int e = beg;
        for (; e + 1 < end; e += 2) {
            int   s0 = __ldg(&g_srcs[e]),     s1 = __ldg(&g_srcs[e + 1]);
            float w0 = __ldg(&g_normv[e]),    w1 = __ldg(&g_normv[e + 1]);
            float4 v0 = *((const float4*)(h + (size_t)s0 * F) + lane);
            float4 v1 = *((const float4*)(h + (size_t)s1 * F) + lane);
            acc.x += v0.x * w0 + v1.x * w1;
            acc.y += v0.y * w0 + v1.y * w1;
            acc.z += v0.z * w0 + v1.z * w1;
            acc.w += v0.w * w0 + v1.w * w1;
        }
        if (e < end) {
            int   s = __ldg(&g_srcs[e]);
            float w = __ldg(&g_normv[e]);
            float4 v = *((const float4*)(h + (size_t)s * F) + lane);
            acc.x += v.x * w; acc.y += v.y * w; acc.z += v.z * w; acc.w += v.w * w;
        }
        if (FINAL) {
            float4 bb = *((const float4*)bias + lane);
            acc.x = fmaxf(acc.x + bb.x, 0.0f);
            acc.y = fmaxf(acc.y + bb.y, 0.0f);
            acc.z = fmaxf(acc.z + bb.z, 0.0f);
            acc.w = fmaxf(acc.w + bb.w, 0.0f);
        }
        *((float4*)(out + (size_t)warp * F) + lane) = acc;
    } else {  // F == 64: float2 per lane
        const float2* hr = (const float2*)(h + (size_t)warp * F) + lane;
        float2 hv = *hr;
        float2 acc = make_float2(hv.x * dd, hv.y * dd);
        int e = beg;
        for (; e + 1 < end; e += 2) {
            int   s0 = __ldg(&g_srcs[e]),     s1 = __ldg(&g_srcs[e + 1]);
            float w0 = __ldg(&g_normv[e]),    w1 = __ldg(&g_normv[e + 1]);
            float2 v0 = *((const float2*)(h + (size_t)s0 * F) + lane);
            float2 v1 = *((const float2*)(h + (size_t)s1 * F) + lane);
            acc.x += v0.x * w0 + v1.x * w1;
            acc.y += v0.y * w0 + v1.y * w1;
        }
        if (e < end) {
            int   s = __ldg(&g_srcs[e]);
            float w = __ldg(&g_normv[e]);
            float2 v = *((const float2*)(h + (size_t)s * F) + lane);
            acc.x += v.x * w; acc.y += v.y * w;
        }
        if (FINAL) {
            float2 bb = *((const float2*)bias + lane);
            acc.x = fmaxf(acc.x + bb.x, 0.0f);
            acc.y = fmaxf(acc.y + bb.y, 0.0f);
        }
        *((float2*)(out + (size_t)warp * F) + lane) = acc;
    }
}

// ---------------------------------------------------------------------------
// Tiled SGEMM with packed FFMA2: H = act(A)[M,128] @ W[128,BN].
// BM=128, BK=16, TM=8; single-buffered smem, conflict-free A-tile STS.
// If FUSE: act(a) = relu(a + bias[k]) applied on A-tile load.
// ---------------------------------------------------------------------------
template <int BN, int TN, bool FUSE>
__global__ void k_gemm_fused(const float* __restrict__ A,
                             const float* __restrict__ W,
                             const float* __restrict__ bias,
                             float* __restrict__ H,
                             int M) {
    constexpr int BM = 128, BK = 16, TM = 8;
    constexpr int TX  = BN / TN;
    constexpr int TNP = TN / 2;
    static_assert(TX * (BM / TM) == 256, "block must be 256 threads");
    constexpr int BV  = BN / 4;
    constexpr int NLB = (BK * BV) / 256;

    __shared__ float As[BK][BM];
    __shared__ float Bs[BK][BN];

    const int tid  = threadIdx.x;
    const int ty   = tid / TX;
    const int tx   = tid % TX;
    const int row0 = blockIdx.x * BM;

    const int ar  = tid & 127;
    const int ac0 = (tid >> 7) * 4;
    const int agrow = row0 + ar;
    const bool arow_ok = (agrow < M);
    const float* Arow = A + (size_t)agrow * 128;

    unsigned long long acc2[TM][TNP];
#pragma unroll
    for (int m = 0; m < TM; m++)
#pragma unroll
        for (int j = 0; j < TNP; j++) acc2[m][j] = 0ull;

    for (int k0 = 0; k0 < 128; k0 += BK) {
        float4 pa[2];
#pragma unroll
        for (int i = 0; i < 2; i++) {
            int c = ac0 + i * 8;
            float4 v = make_float4(0.f, 0.f, 0.f, 0.f);
            if (arow_ok) {
                v = *(const float4*)(Arow + k0 + c);
                if (FUSE) {
                    float4 bb = *(const float4*)(bias + k0 + c);
                    v.x = fmaxf(v.x + bb.x, 0.0f);
                    v.y = fmaxf(v.y + bb.y, 0.0f);
                    v.z = fmaxf(v.z + bb.z, 0.0f);
                    v.w = fmaxf(v.w + bb.w, 0.0f);
                }
            }
            pa[i] = v;
        }
        float4 pb[NLB];
#pragma unroll
        for (int i = 0; i < NLB; i++) {
            int l = tid + i * 256;
            int r = l / BV;
            int c = (l % BV) * 4;
            pb[i] = *(const float4*)(W + (size_t)(k0 + r) * BN + c);
        }

        __syncthreads();
#pragma unroll
        for (int i = 0; i < 2; i++) {
            int c = ac0 + i * 8;
            As[c + 0][ar] = pa[i].x;
            As[c + 1][ar] = pa[i].y;
            As[c + 2][ar] = pa[i].z;
            As[c + 3][ar] = pa[i].w;
        }
#pragma unroll
        for (int i = 0; i < NLB; i++) {
            int l = tid + i * 256;
            int r = l / BV;
            int c = (l % BV) * 4;
            *(float4*)(&Bs[r][c]) = pb[i];
        }
        __syncthreads();

#pragma unroll
        for (int k = 0; k < BK; k++) {
            float4 a0 = *(const float4*)(&As[k][ty * TM]);
            float4 a1 = *(const float4*)(&As[k][ty * TM + 4]);
            unsigned long long bn2[TNP];
            {
                const ulonglong2* bp = (const ulonglong2*)(&Bs[k][tx * TN]);
                ulonglong2 t0 = bp[0];
                bn2[0] = t0.x; bn2[1] = t0.y;
                if (TNP == 4) {
                    ulonglong2 t1 = bp[1];
                    bn2[2] = t1.x; bn2[3] = t1.y;
                }
            }
            float am[TM] = {a0.x, a0.y, a0.z, a0.w, a1.x, a1.y, a1.z, a1.w};
#pragma unroll
            for (int m = 0; m < TM; m++) {
                unsigned long long a2 = dup2(am[m]);
#pragma unroll
                for (int j = 0; j < TNP; j++)
                    acc2[m][j] = ffma2(a2, bn2[j], acc2[m][j]);
            }
        }
    }

#pragma unroll
    for (int m = 0; m < TM; m++) {
        int grow = row0 + ty * TM + m;
        if (grow < M) {
#pragma unroll
            for (int j = 0; j < TNP; j += 2) {
                float2 p0 = unpack2(acc2[m][j]);
                float2 p1 = unpack2(acc2[m][j + 1]);
                float4 v = make_float4(p0.x, p0.y, p1.x, p1.y);
                int col = tx * TN + j * 2;
                *(float4*)(H + (size_t)grow * BN + col) = v;
            }
        }
    }
}

// ---------------------------------------------------------------------------
// launch
// ---------------------------------------------------------------------------
extern "C" void kernel_launch(void* const* d_in, const int* in_sizes, int n_in,
                              void* d_out, int out_size) {
    const float* x  = (const float*)d_in[0];
    const int*   ei = (const int*)  d_in[1];
    const float* W1 = (const float*)d_in[2];
    const float* b1 = (const float*)d_in[3];
    const float* W2 = (const float*)d_in[4];
    const float* b2 = (const float*)d_in[5];
    float* out = (float*)d_out;

    const int N = in_sizes[0] / F_IN;
    const int E = in_sizes[1] / 2;

    float *p_h1, *p_agg, *p_h3;
    cudaGetSymbolAddress((void**)&p_h1,  g_h1);
    cudaGetSymbolAddress((void**)&p_agg, g_agg);
    cudaGetSymbolAddress((void**)&p_h3,  g_h3);

    const int T = 256;
    const int nScanBlocks = (N + 1023) / 1024;

    // ---- degrees -> dinv -> CSR ----
    k_deg_zero  <<<(N + T - 1) / T, T>>>(N);
    k_deg_count <<<(E + T - 1) / T, T>>>(ei, E);
    k_dinv      <<<(N + T - 1) / T, T>>>(N);
    k_scan_local<<<nScanBlocks, 1024>>>(N);
    k_scan_bsums<<<1, 32>>>(nScanBlocks);
    k_scan_add  <<<nScanBlocks, 1024>>>(N, E);
    k_fill      <<<(E + T - 1) / T, T>>>(ei, E);

    // ---- layer 1: GEMM -> gather (raw agg; relu+b1 fused into GEMM2 load) ----
    k_gemm_fused<F_HID, 8, false><<<(N + 127) / 128, 256>>>(x, W1, nullptr, p_h1, N);
    k_gather<F_HID, false><<<(N + 7) / 8, 256>>>(p_h1, nullptr, p_agg, N);

    // ---- layer 2: GEMM (fused relu(agg+b1)) -> gather (fused relu(+b2)) ----
    k_gemm_fused<F_OUT, 4, true><<<(N + 127) / 128, 256>>>(p_agg, W2, b1, p_h3, N);
    k_gather<F_OUT, true><<<(N + 7) / 8, 256>>>(p_h3, b2, out, N);
}

// round 14
// speedup vs baseline: 1.8722x; 1.1183x over previous
#include <cuda_runtime.h>
#include <cuda_bf16.h>
#include <cstdint>

// Problem constants
#define MAX_N 50000
#define MAX_E 800000
#define F_IN  128
#define F_HID 128
#define F_OUT 64

// Scratch (device globals; no allocation allowed in kernel_launch)
__device__ float g_h1 [MAX_N * F_HID];
__device__ float g_agg[MAX_N * F_HID];
__device__ float g_h3 [MAX_N * F_OUT];
__device__ float g_dinv[MAX_N];
__device__ int   g_deg [MAX_N];
// CSR (edges sorted by dst)
__device__ int   g_rowptr[MAX_N + 1];
__device__ int   g_cursor[MAX_N];
__device__ int   g_srcs  [MAX_E];
__device__ float g_normv [MAX_E];
__device__ int   g_bsum  [64];
// Pre-split bf16 weights, [k][n] row-major (same layout as the fp32 inputs)
__device__ __nv_bfloat16 g_w1hi[128 * 128];
__device__ __nv_bfloat16 g_w1lo[128 * 128];
__device__ __nv_bfloat16 g_w2hi[128 * 64];
__device__ __nv_bfloat16 g_w2lo[128 * 64];

// ---------------------------------------------------------------------------
// helpers
// ---------------------------------------------------------------------------
__device__ __forceinline__ uint32_t smem_u32(const void* p) {
    uint32_t a;
    asm("{ .reg .u64 t; cvta.to.shared.u64 t, %1; cvt.u32.u64 %0, t; }"
        : "=r"(a) : "l"(p));
    return a;
}

__device__ __forceinline__ void split_pack(float a, float b, uint32_t& hi, uint32_t& lo) {
    __nv_bfloat16 ha = __float2bfloat16_rn(a), hb = __float2bfloat16_rn(b);
    float ra = a - __bfloat162float(ha);
    float rb = b - __bfloat162float(hb);
    __nv_bfloat16 la = __float2bfloat16_rn(ra), lb = __float2bfloat16_rn(rb);
    unsigned short uha = *(unsigned short*)&ha, uhb = *(unsigned short*)&hb;
    unsigned short ula = *(unsigned short*)&la, ulb = *(unsigned short*)&lb;
    hi = ((uint32_t)uhb << 16) | uha;
    lo = ((uint32_t)ulb << 16) | ula;
}

__device__ __forceinline__ void ldsm_x4(uint32_t* r, uint32_t addr) {
    asm volatile("ldmatrix.sync.aligned.m8n8.x4.shared.b16 {%0,%1,%2,%3}, [%4];"
                 : "=r"(r[0]), "=r"(r[1]), "=r"(r[2]), "=r"(r[3]) : "r"(addr));
}
__device__ __forceinline__ void ldsm_x4_t(uint32_t* r, uint32_t addr) {
    asm volatile("ldmatrix.sync.aligned.m8n8.x4.trans.shared.b16 {%0,%1,%2,%3}, [%4];"
                 : "=r"(r[0]), "=r"(r[1]), "=r"(r[2]), "=r"(r[3]) : "r"(addr));
}
__device__ __forceinline__ void mma_bf16(float* d, const uint32_t* a, const uint32_t* b) {
    asm volatile(
        "mma.sync.aligned.m16n8k16.row.col.f32.bf16.bf16.f32 "
        "{%0,%1,%2,%3}, {%4,%5,%6,%7}, {%8,%9}, {%0,%1,%2,%3};"
        : "+f"(d[0]), "+f"(d[1]), "+f"(d[2]), "+f"(d[3])
        : "r"(a[0]), "r"(a[1]), "r"(a[2]), "r"(a[3]), "r"(b[0]), "r"(b[1]));
}

// ---------------------------------------------------------------------------
// degree / dinv / scan / CSR fill (unchanged from R10 winner)
// ---------------------------------------------------------------------------
__global__ void k_deg_zero(int n) {
    int i = blockIdx.x * blockDim.x + threadIdx.x;
    if (i < n) g_deg[i] = 0;
}
__global__ void k_deg_count(const int* __restrict__ ei, int E) {
    int e = blockIdx.x * blockDim.x + threadIdx.x;
    if (e < E) atomicAdd(&g_deg[ei[E + e]], 1);
}
__global__ void k_dinv(int n) {
    int i = blockIdx.x * blockDim.x + threadIdx.x;
    if (i < n) g_dinv[i] = rsqrtf((float)g_deg[i] + 1.0f);
}
__global__ void k_scan_local(int n) {
    int i = blockIdx.x * 1024 + threadIdx.x;
    int v = (i < n) ? g_deg[i] : 0;
    int lane = threadIdx.x & 31, wid = threadIdx.x >> 5;
    int x = v;
#pragma unroll
    for (int o = 1; o < 32; o <<= 1) {
        int t = __shfl_up_sync(0xffffffffu, x, o);
        if (lane >= o) x += t;
    }
    __shared__ int wsum[32];
    if (lane == 31) wsum[wid] = x;
    __syncthreads();
    if (wid == 0) {
        int y = wsum[lane];
#pragma unroll
        for (int o = 1; o < 32; o <<= 1) {
            int t = __shfl_up_sync(0xffffffffu, y, o);
            if (lane >= o) y += t;
        }
        wsum[lane] = y;
    }
    __syncthreads();
    int incl = x + (wid > 0 ? wsum[wid - 1] : 0);
    if (i < n) g_rowptr[i] = incl - v;
    if (threadIdx.x == 1023) g_bsum[blockIdx.x] = incl;
}
__global__ void k_scan_bsums(int nb) {
    if (threadIdx.x == 0) {
        int run = 0;
        for (int b = 0; b < nb; b++) { int t = g_bsum[b]; g_bsum[b] = run; run += t; }
    }
}
__global__ void k_scan_add(int n, int E) {
    int i = blockIdx.x * 1024 + threadIdx.x;
    if (i < n) {
        int rp = g_rowptr[i] + g_bsum[blockIdx.x];
        g_rowptr[i] = rp;
        g_cursor[i] = rp;
    }
    if (i == 0) g_rowptr[n] = E;
}
__global__ void k_fill(const int* __restrict__ ei, int E) {
    int e = blockIdx.x * blockDim.x + threadIdx.x;
    if (e >= E) return;
    int src = ei[e];
    int dst = ei[E + e];
    int pos = atomicAdd(&g_cursor[dst], 1);
    g_srcs[pos]  = src;
    g_normv[pos] = g_dinv[src] * g_dinv[dst];
}

// ---------------------------------------------------------------------------
// CSR gather (unchanged from R10 winner)
// ---------------------------------------------------------------------------
template <int F, bool FINAL>
__global__ void k_gather(const float* __restrict__ h,
                         const float* __restrict__ bias,
                         float* __restrict__ out, int N) {
    int warp = (blockIdx.x * blockDim.x + threadIdx.x) >> 5;
    int lane = threadIdx.x & 31;
    if (warp >= N) return;
    int beg = g_rowptr[warp];
    int end = g_rowptr[warp + 1];
    float d = g_dinv[warp];
    float dd = d * d;

    if (F == 128) {
        float4 hv = *((const float4*)(h + (size_t)warp * F) + lane);
        float4 acc = make_float4(hv.x * dd, hv.y * dd, hv.z * dd, hv.w * dd);
        int e = beg;
        for (; e + 1 < end; e += 2) {
            int   s0 = __ldg(&g_srcs[e]),  s1 = __ldg(&g_srcs[e + 1]);
            float w0 = __ldg(&g_normv[e]), w1 = __ldg(&g_normv[e + 1]);
            float4 v0 = *((const float4*)(h + (size_t)s0 * F) + lane);
            float4 v1 = *((const float4*)(h + (size_t)s1 * F) + lane);
            acc.x += v0.x * w0 + v1.x * w1;
            acc.y += v0.y * w0 + v1.y * w1;
            acc.z += v0.z * w0 + v1.z * w1;
            acc.w += v0.w * w0 + v1.w * w1;
        }
        if (e < end) {
            int   s = __ldg(&g_srcs[e]);
            float w = __ldg(&g_normv[e]);
            float4 v = *((const float4*)(h + (size_t)s * F) + lane);
            acc.x += v.x * w; acc.y += v.y * w; acc.z += v.z * w; acc.w += v.w * w;
        }
        if (FINAL) {
            float4 bb = *((const float4*)bias + lane);
            acc.x = fmaxf(acc.x + bb.x, 0.0f);
            acc.y = fmaxf(acc.y + bb.y, 0.0f);
            acc.z = fmaxf(acc.z + bb.z, 0.0f);
            acc.w = fmaxf(acc.w + bb.w, 0.0f);
        }
        *((float4*)(out + (size_t)warp * F) + lane) = acc;
    } else {
        float2 hv = *((const float2*)(h + (size_t)warp * F) + lane);
        float2 acc = make_float2(hv.x * dd, hv.y * dd);
        int e = beg;
        for (; e + 1 < end; e += 2) {
            int   s0 = __ldg(&g_srcs[e]),  s1 = __ldg(&g_srcs[e + 1]);
            float w0 = __ldg(&g_normv[e]), w1 = __ldg(&g_normv[e + 1]);
            float2 v0 = *((const float2*)(h + (size_t)s0 * F) + lane);
            float2 v1 = *((const float2*)(h + (size_t)s1 * F) + lane);
            acc.x += v0.x * w0 + v1.x * w1;
            acc.y += v0.y * w0 + v1.y * w1;
        }
        if (e < end) {
            int   s = __ldg(&g_srcs[e]);
            float w = __ldg(&g_normv[e]);
            float2 v = *((const float2*)(h + (size_t)s * F) + lane);
            acc.x += v.x * w; acc.y += v.y * w;
        }
        if (FINAL) {
            float2 bb = *((const float2*)bias + lane);
            acc.x = fmaxf(acc.x + bb.x, 0.0f);
            acc.y = fmaxf(acc.y + bb.y, 0.0f);
        }
        *((float2*)(out + (size_t)warp * F) + lane) = acc;
    }
}

// ---------------------------------------------------------------------------
// Weight prep: elementwise split into bf16 hi/lo, [k][n] row-major (same as src)
// ---------------------------------------------------------------------------
__global__ void k_prep_w(const float* __restrict__ W1, const float* __restrict__ W2) {
    int i = blockIdx.x * blockDim.x + threadIdx.x;
    if (i < 128 * 128) {
        float v = W1[i];
        __nv_bfloat16 h = __float2bfloat16_rn(v);
        g_w1hi[i] = h;
        g_w1lo[i] = __float2bfloat16_rn(v - __bfloat162float(h));
    } else {
        int j = i - 128 * 128;
        if (j < 128 * 64) {
            float v = W2[j];
            __nv_bfloat16 h = __float2bfloat16_rn(v);
            g_w2hi[j] = h;
            g_w2lo[j] = __float2bfloat16_rn(v - __bfloat162float(h));
        }
    }
}

// ---------------------------------------------------------------------------
// Split-bf16 HMMA GEMM: H[M,BN] = act(A)[M,128] @ W[128,BN]
// 3 terms: Ahi*Whi + Ahi*Wlo + Alo*Whi, fp32 accum in registers.
// Block 128xBN, 256 threads = 8 warps (4 along M x 2 along N).
// Padded smem (stride +16B) -> conflict-free ldmatrix.
// If FUSE: act(a) = relu(a + bias[k]) on A-tile load.
// ---------------------------------------------------------------------------
template <int BN, bool FUSE>
__global__ void __launch_bounds__(256)
k_gemm_mma(const float* __restrict__ A,
           const __nv_bfloat16* __restrict__ Whi,
           const __nv_bfloat16* __restrict__ Wlo,
           const float* __restrict__ bias,
           float* __restrict__ H, int M) {
    constexpr int ASTR = 272;                  // 128 bf16 + 16B pad
    constexpr int BSTR = BN * 2 + 16;
    constexpr int ASZ  = 128 * ASTR;           // 34816 B per A tile
    constexpr int BSZ  = 128 * BSTR;           // per W tile
    constexpr int NW   = BN / 2;               // warp n-width (64 / 32)
    constexpr int NF   = NW / 8;               // n8 frags per warp (8 / 4)
    constexpr int NB   = NW / 16;              // x4 B loads per k-step (4 / 2)

    extern __shared__ char smem[];
    const uint32_t sb   = smem_u32(smem);
    const uint32_t pAhi = sb;
    const uint32_t pAlo = sb + ASZ;
    const uint32_t pBhi = sb + 2 * ASZ;
    const uint32_t pBlo = sb + 2 * ASZ + BSZ;

    const int tid  = threadIdx.x;
    const int lane = tid & 31;
    const int wid  = tid >> 5;
    const int wm   = wid & 3;                  // warp row group (0..3)
    const int wn   = wid >> 2;                 // warp col group (0..1)
    const int row0 = blockIdx.x * 128;

    // ---- A load + split-convert: 128 rows x 32 float4 ----
#pragma unroll
    for (int i = 0; i < 16; i++) {
        int idx  = tid + i * 256;
        int row  = idx >> 5;
        int col4 = (idx & 31) * 4;
        float4 v = make_float4(0.f, 0.f, 0.f, 0.f);
        if (row0 + row < M) {
            v = *(const float4*)(A + (size_t)(row0 + row) * 128 + col4);
            if (FUSE) {
                float4 bb = *(const float4*)(bias + col4);
                v.x = fmaxf(v.x + bb.x, 0.0f);
                v.y = fmaxf(v.y + bb.y, 0.0f);
                v.z = fmaxf(v.z + bb.z, 0.0f);
                v.w = fmaxf(v.w + bb.w, 0.0f);
            }
        }
        uint32_t h01, l01, h23, l23;
        split_pack(v.x, v.y, h01, l01);
        split_pack(v.z, v.w, h23, l23);
        uint32_t off = row * ASTR + col4 * 2;
        *(uint2*)(smem + off)       = make_uint2(h01, h23);
        *(uint2*)(smem + ASZ + off) = make_uint2(l01, l23);
    }

    // ---- W tiles: copy pre-split bf16 into padded smem ----
    {
        constexpr int ROWB = BN * 2;           // data bytes per k-row
        constexpr int VPR  = ROWB / 16;        // uint4 per row
        for (int u = tid; u < 2 * 128 * VPR; u += 256) {
            int t = u / (128 * VPR);           // 0 = hi, 1 = lo
            int v = u % (128 * VPR);
            int r = v / VPR;
            int o = (v % VPR) * 16;
            const char* src = (const char*)(t ? Wlo : Whi) + r * ROWB + o;
            char* dst = smem + (2 * ASZ + t * BSZ) + r * BSTR + o;
            *(uint4*)dst = *(const uint4*)src;
        }
    }
    __syncthreads();

    // ---- 3-term HMMA sweep ----
    float d[2][NF][4];
#pragma unroll
    for (int mi = 0; mi < 2; mi++)
#pragma unroll
        for (int nf = 0; nf < NF; nf++)
#pragma unroll
            for (int c = 0; c < 4; c++) d[mi][nf][c] = 0.0f;

    const int li = lane & 7;
    const int q  = lane >> 3;
    const int r8 = (q & 1) * 8 + li;           // row offset within 16x16
    const int c8 = (q >> 1) * 8;               // col offset within 16x16

#pragma unroll
    for (int term = 0; term < 3; term++) {
        uint32_t At = (term == 2) ? pAlo : pAhi;
        uint32_t Bt = (term == 1) ? pBlo : pBhi;
#pragma unroll
        for (int kb = 0; kb < 128; kb += 16) {
            uint32_t a[2][4];
#pragma unroll
            for (int mi = 0; mi < 2; mi++)
                ldsm_x4(a[mi], At + (uint32_t)(wm * 32 + mi * 16 + r8) * ASTR
                                  + (kb + c8) * 2);
            uint32_t b[NB][4];
#pragma unroll
            for (int nb = 0; nb < NB; nb++)
                ldsm_x4_t(b[nb], Bt + (uint32_t)(kb + r8) * BSTR
                                    + (wn * NW + nb * 16 + c8) * 2);
#pragma unroll
            for (int mi = 0; mi < 2; mi++)
#pragma unroll
                for (int nf = 0; nf < NF; nf++)
                    mma_bf16(d[mi][nf], a[mi], &b[nf >> 1][(nf & 1) * 2]);
        }
    }

    // ---- epilogue: D regs -> global ----
    const int g   = lane >> 2;
    const int tig = lane & 3;
#pragma unroll
    for (int mi = 0; mi < 2; mi++) {
        int r1 = row0 + wm * 32 + mi * 16 + g;
#pragma unroll
        for (int nf = 0; nf < NF; nf++) {
            int col = wn * NW + nf * 8 + tig * 2;
            if (r1 < M)
                *(float2*)(H + (size_t)r1 * BN + col) =
                    make_float2(d[mi][nf][0], d[mi][nf][1]);
            if (r1 + 8 < M)
                *(float2*)(H + (size_t)(r1 + 8) * BN + col) =
                    make_float2(d[mi][nf][2], d[mi][nf][3]);
        }
    }
}

// ---------------------------------------------------------------------------
// launch
// ---------------------------------------------------------------------------
extern "C" void kernel_launch(void* const* d_in, const int* in_sizes, int n_in,
                              void* d_out, int out_size) {
    const float* x  = (const float*)d_in[0];
    const int*   ei = (const int*)  d_in[1];
    const float* W1 = (const float*)d_in[2];
    const float* b1 = (const float*)d_in[3];
    const float* W2 = (const float*)d_in[4];
    const float* b2 = (const float*)d_in[5];
    float* out = (float*)d_out;

    const int N = in_sizes[0] / F_IN;
    const int E = in_sizes[1] / 2;

    float *p_h1, *p_agg, *p_h3;
    cudaGetSymbolAddress((void**)&p_h1,  g_h1);
    cudaGetSymbolAddress((void**)&p_agg, g_agg);
    cudaGetSymbolAddress((void**)&p_h3,  g_h3);
    __nv_bfloat16 *p_w1h, *p_w1l, *p_w2h, *p_w2l;
    cudaGetSymbolAddress((void**)&p_w1h, g_w1hi);
    cudaGetSymbolAddress((void**)&p_w1l, g_w1lo);
    cudaGetSymbolAddress((void**)&p_w2h, g_w2hi);
    cudaGetSymbolAddress((void**)&p_w2l, g_w2lo);

    const int T = 256;
    const int nScanBlocks = (N + 1023) / 1024;

    // smem: 2 A tiles (34816 each) + 2 W tiles
    const int smem1 = 2 * 34816 + 2 * 128 * (128 * 2 + 16);  // 139,264
    const int smem2 = 2 * 34816 + 2 * 128 * (64 * 2 + 16);   // 106,496
    cudaFuncSetAttribute(k_gemm_mma<128, false>,
                         cudaFuncAttributeMaxDynamicSharedMemorySize, smem1);
    cudaFuncSetAttribute(k_gemm_mma<64, true>,
                         cudaFuncAttributeMaxDynamicSharedMemorySize, smem2);

    // ---- degrees -> dinv -> CSR ----
    k_deg_zero  <<<(N + T - 1) / T, T>>>(N);
    k_deg_count <<<(E + T - 1) / T, T>>>(ei, E);
    k_dinv      <<<(N + T - 1) / T, T>>>(N);
    k_scan_local<<<nScanBlocks, 1024>>>(N);
    k_scan_bsums<<<1, 32>>>(nScanBlocks);
    k_scan_add  <<<nScanBlocks, 1024>>>(N, E);
    k_fill      <<<(E + T - 1) / T, T>>>(ei, E);

    // ---- weight prep ----
    k_prep_w<<<(128 * 128 + 128 * 64 + T - 1) / T, T>>>(W1, W2);

    // ---- layer 1: HMMA GEMM -> gather ----
    k_gemm_mma<128, false><<<(N + 127) / 128, 256, smem1>>>(x, p_w1h, p_w1l,
                                                            nullptr, p_h1, N);
    k_gather<F_HID, false><<<(N + 7) / 8, 256>>>(p_h1, nullptr, p_agg, N);

    // ---- layer 2: HMMA GEMM (fused relu(agg+b1)) -> gather (fused relu+b2) ----
    k_gemm_mma<64, true><<<(N + 127) / 128, 256, smem2>>>(p_agg, p_w2h, p_w2l,
                                                          b1, p_h3, N);
    k_gather<F_OUT, true><<<(N + 7) / 8, 256>>>(p_h3, b2, out, N);
}

// round 15
// speedup vs baseline: 2.0122x; 1.0748x over previous
#include <cuda_runtime.h>
#include <cuda_bf16.h>
#include <cstdint>

// Problem constants
#define MAX_N 50000
#define MAX_E 800000
#define F_IN  128
#define F_HID 128
#define F_OUT 64

// Scratch (device globals; no allocation allowed in kernel_launch)
__device__ float g_h1 [MAX_N * F_HID];
__device__ float g_agg[MAX_N * F_HID];
__device__ float g_h3 [MAX_N * F_OUT];
__device__ float g_dinv[MAX_N];
__device__ int   g_deg [MAX_N];
// CSR (edges sorted by dst)
__device__ int   g_rowptr[MAX_N + 1];
__device__ int   g_cursor[MAX_N];
__device__ int   g_srcs  [MAX_E];
__device__ float g_normv [MAX_E];
__device__ int   g_bsum  [64];
// Pre-split bf16 weights, [k][n] row-major (same layout as the fp32 inputs)
__device__ __nv_bfloat16 g_w1hi[128 * 128];
__device__ __nv_bfloat16 g_w1lo[128 * 128];
__device__ __nv_bfloat16 g_w2hi[128 * 64];
__device__ __nv_bfloat16 g_w2lo[128 * 64];

// ---------------------------------------------------------------------------
// helpers
// ---------------------------------------------------------------------------
__device__ __forceinline__ uint32_t smem_u32(const void* p) {
    uint32_t a;
    asm("{ .reg .u64 t; cvta.to.shared.u64 t, %1; cvt.u32.u64 %0, t; }"
        : "=r"(a) : "l"(p));
    return a;
}

__device__ __forceinline__ void split_pack(float a, float b, uint32_t& hi, uint32_t& lo) {
    __nv_bfloat16 ha = __float2bfloat16_rn(a), hb = __float2bfloat16_rn(b);
    float ra = a - __bfloat162float(ha);
    float rb = b - __bfloat162float(hb);
    __nv_bfloat16 la = __float2bfloat16_rn(ra), lb = __float2bfloat16_rn(rb);
    unsigned short uha = *(unsigned short*)&ha, uhb = *(unsigned short*)&hb;
    unsigned short ula = *(unsigned short*)&la, ulb = *(unsigned short*)&lb;
    hi = ((uint32_t)uhb << 16) | uha;
    lo = ((uint32_t)ulb << 16) | ula;
}

__device__ __forceinline__ void ldsm_x4(uint32_t* r, uint32_t addr) {
    asm volatile("ldmatrix.sync.aligned.m8n8.x4.shared.b16 {%0,%1,%2,%3}, [%4];"
                 : "=r"(r[0]), "=r"(r[1]), "=r"(r[2]), "=r"(r[3]) : "r"(addr));
}
__device__ __forceinline__ void ldsm_x4_t(uint32_t* r, uint32_t addr) {
    asm volatile("ldmatrix.sync.aligned.m8n8.x4.trans.shared.b16 {%0,%1,%2,%3}, [%4];"
                 : "=r"(r[0]), "=r"(r[1]), "=r"(r[2]), "=r"(r[3]) : "r"(addr));
}
__device__ __forceinline__ void mma_bf16(float* d, const uint32_t* a, const uint32_t* b) {
    asm volatile(
        "mma.sync.aligned.m16n8k16.row.col.f32.bf16.bf16.f32 "
        "{%0,%1,%2,%3}, {%4,%5,%6,%7}, {%8,%9}, {%0,%1,%2,%3};"
        : "+f"(d[0]), "+f"(d[1]), "+f"(d[2]), "+f"(d[3])
        : "r"(a[0]), "r"(a[1]), "r"(a[2]), "r"(a[3]), "r"(b[0]), "r"(b[1]));
}

// ---------------------------------------------------------------------------
// degree / scan / CSR fill  (dinv fused into scan_local)
// ---------------------------------------------------------------------------
__global__ void k_deg_zero(int n) {
    int i = blockIdx.x * blockDim.x + threadIdx.x;
    if (i < n) g_deg[i] = 0;
}
__global__ void k_deg_count(const int* __restrict__ ei, int E) {
    int e = blockIdx.x * blockDim.x + threadIdx.x;
    if (e < E) atomicAdd(&g_deg[ei[E + e]], 1);
}
__global__ void k_scan_local(int n) {
    int i = blockIdx.x * 1024 + threadIdx.x;
    int v = (i < n) ? g_deg[i] : 0;
    if (i < n) g_dinv[i] = rsqrtf((float)v + 1.0f);   // fused dinv (+1 self loop)
    int lane = threadIdx.x & 31, wid = threadIdx.x >> 5;
    int x = v;
#pragma unroll
    for (int o = 1; o < 32; o <<= 1) {
        int t = __shfl_up_sync(0xffffffffu, x, o);
        if (lane >= o) x += t;
    }
    __shared__ int wsum[32];
    if (lane == 31) wsum[wid] = x;
    __syncthreads();
    if (wid == 0) {
        int y = wsum[lane];
#pragma unroll
        for (int o = 1; o < 32; o <<= 1) {
            int t = __shfl_up_sync(0xffffffffu, y, o);
            if (lane >= o) y += t;
        }
        wsum[lane] = y;
    }
    __syncthreads();
    int incl = x + (wid > 0 ? wsum[wid - 1] : 0);
    if (i < n) g_rowptr[i] = incl - v;
    if (threadIdx.x == 1023) g_bsum[blockIdx.x] = incl;
}
__global__ void k_scan_bsums(int nb) {
    if (threadIdx.x == 0) {
        int run = 0;
        for (int b = 0; b < nb; b++) { int t = g_bsum[b]; g_bsum[b] = run; run += t; }
    }
}
__global__ void k_scan_add(int n, int E) {
    int i = blockIdx.x * 1024 + threadIdx.x;
    if (i < n) {
        int rp = g_rowptr[i] + g_bsum[blockIdx.x];
        g_rowptr[i] = rp;
        g_cursor[i] = rp;
    }
    if (i == 0) g_rowptr[n] = E;
}
__global__ void k_fill(const int* __restrict__ ei, int E) {
    int e = blockIdx.x * blockDim.x + threadIdx.x;
    if (e >= E) return;
    int src = ei[e];
    int dst = ei[E + e];
    int pos = atomicAdd(&g_cursor[dst], 1);
    g_srcs[pos]  = src;
    g_normv[pos] = g_dinv[src] * g_dinv[dst];
}

// ---------------------------------------------------------------------------
// CSR gather (unchanged from R10 winner)
// ---------------------------------------------------------------------------
template <int F, bool FINAL>
__global__ void k_gather(const float* __restrict__ h,
                         const float* __restrict__ bias,
                         float* __restrict__ out, int N) {
    int warp = (blockIdx.x * blockDim.x + threadIdx.x) >> 5;
    int lane = threadIdx.x & 31;
    if (warp >= N) return;
    int beg = g_rowptr[warp];
    int end = g_rowptr[warp + 1];
    float d = g_dinv[warp];
    float dd = d * d;

    if (F == 128) {
        float4 hv = *((const float4*)(h + (size_t)warp * F) + lane);
        float4 acc = make_float4(hv.x * dd, hv.y * dd, hv.z * dd, hv.w * dd);
        int e = beg;
        for (; e + 1 < end; e += 2) {
            int   s0 = __ldg(&g_srcs[e]),  s1 = __ldg(&g_srcs[e + 1]);
            float w0 = __ldg(&g_normv[e]), w1 = __ldg(&g_normv[e + 1]);
            float4 v0 = *((const float4*)(h + (size_t)s0 * F) + lane);
            float4 v1 = *((const float4*)(h + (size_t)s1 * F) + lane);
            acc.x += v0.x * w0 + v1.x * w1;
            acc.y += v0.y * w0 + v1.y * w1;
            acc.z += v0.z * w0 + v1.z * w1;
            acc.w += v0.w * w0 + v1.w * w1;
        }
        if (e < end) {
            int   s = __ldg(&g_srcs[e]);
            float w = __ldg(&g_normv[e]);
            float4 v = *((const float4*)(h + (size_t)s * F) + lane);
            acc.x += v.x * w; acc.y += v.y * w; acc.z += v.z * w; acc.w += v.w * w;
        }
        if (FINAL) {
            float4 bb = *((const float4*)bias + lane);
            acc.x = fmaxf(acc.x + bb.x, 0.0f);
            acc.y = fmaxf(acc.y + bb.y, 0.0f);
            acc.z = fmaxf(acc.z + bb.z, 0.0f);
            acc.w = fmaxf(acc.w + bb.w, 0.0f);
        }
        *((float4*)(out + (size_t)warp * F) + lane) = acc;
    } else {
        float2 hv = *((const float2*)(h + (size_t)warp * F) + lane);
        float2 acc = make_float2(hv.x * dd, hv.y * dd);
        int e = beg;
        for (; e + 1 < end; e += 2) {
            int   s0 = __ldg(&g_srcs[e]),  s1 = __ldg(&g_srcs[e + 1]);
            float w0 = __ldg(&g_normv[e]), w1 = __ldg(&g_normv[e + 1]);
            float2 v0 = *((const float2*)(h + (size_t)s0 * F) + lane);
            float2 v1 = *((const float2*)(h + (size_t)s1 * F) + lane);
            acc.x += v0.x * w0 + v1.x * w1;
            acc.y += v0.y * w0 + v1.y * w1;
        }
        if (e < end) {
            int   s = __ldg(&g_srcs[e]);
            float w = __ldg(&g_normv[e]);
            float2 v = *((const float2*)(h + (size_t)s * F) + lane);
            acc.x += v.x * w; acc.y += v.y * w;
        }
        if (FINAL) {
            float2 bb = *((const float2*)bias + lane);
            acc.x = fmaxf(acc.x + bb.x, 0.0f);
            acc.y = fmaxf(acc.y + bb.y, 0.0f);
        }
        *((float2*)(out + (size_t)warp * F) + lane) = acc;
    }
}

// ---------------------------------------------------------------------------
// Weight prep: elementwise split into bf16 hi/lo, [k][n] row-major
// ---------------------------------------------------------------------------
__global__ void k_prep_w(const float* __restrict__ W1, const float* __restrict__ W2) {
    int i = blockIdx.x * blockDim.x + threadIdx.x;
    if (i < 128 * 128) {
        float v = W1[i];
        __nv_bfloat16 h = __float2bfloat16_rn(v);
        g_w1hi[i] = h;
        g_w1lo[i] = __float2bfloat16_rn(v - __bfloat162float(h));
    } else {
        int j = i - 128 * 128;
        if (j < 128 * 64) {
            float v = W2[j];
            __nv_bfloat16 h = __float2bfloat16_rn(v);
            g_w2hi[j] = h;
            g_w2lo[j] = __float2bfloat16_rn(v - __bfloat162float(h));
        }
    }
}

// ---------------------------------------------------------------------------
// Split-bf16 HMMA GEMM, K-chunked: H[M,BN] = act(A)[M,128] @ W[128,BN]
// K processed in 2 chunks of 64 -> smem halves -> 2-3 CTAs/SM.
// 3 terms: Ahi*Whi + Ahi*Wlo + Alo*Whi, fp32 accum in registers.
// Block 128xBN, 256 threads = 8 warps (4 along M x 2 along N).
// If FUSE: act(a) = relu(a + bias[k]) on A-tile load.
// ---------------------------------------------------------------------------
template <int BN, bool FUSE>
__global__ void __launch_bounds__(256)
k_gemm_mma(const float* __restrict__ A,
           const __nv_bfloat16* __restrict__ Whi,
           const __nv_bfloat16* __restrict__ Wlo,
           const float* __restrict__ bias,
           float* __restrict__ H, int M) {
    constexpr int KC   = 64;                   // K-chunk width
    constexpr int ASTR = KC * 2 + 16;          // 144 B: 64 bf16 + pad
    constexpr int ASZ  = 128 * ASTR;           // 18432 B per A tile
    constexpr int BSTR = BN * 2 + 16;
    constexpr int BSZ  = KC * BSTR;            // per W tile (64 k-rows)
    constexpr int NW   = BN / 2;               // warp n-width (64 / 32)
    constexpr int NF   = NW / 8;               // n8 frags per warp (8 / 4)
    constexpr int NB   = NW / 16;              // x4 B loads per k-step (4 / 2)

    extern __shared__ char smem[];
    const uint32_t sb   = smem_u32(smem);
    const uint32_t pAhi = sb;
    const uint32_t pAlo = sb + ASZ;
    const uint32_t pBhi = sb + 2 * ASZ;
    const uint32_t pBlo = sb + 2 * ASZ + BSZ;

    const int tid  = threadIdx.x;
    const int lane = tid & 31;
    const int wid  = tid >> 5;
    const int wm   = wid & 3;                  // warp row group (0..3)
    const int wn   = wid >> 2;                 // warp col group (0..1)
    const int row0 = blockIdx.x * 128;

    float d[2][NF][4];
#pragma unroll
    for (int mi = 0; mi < 2; mi++)
#pragma unroll
        for (int nf = 0; nf < NF; nf++)
#pragma unroll
            for (int c = 0; c < 4; c++) d[mi][nf][c] = 0.0f;

    const int li = lane & 7;
    const int q  = lane >> 3;
    const int r8 = (q & 1) * 8 + li;           // row offset within 16x16
    const int c8 = (q >> 1) * 8;               // col offset within 16x16

#pragma unroll
    for (int kc = 0; kc < 128; kc += KC) {
        // ---- A chunk load + split-convert: 128 rows x 16 float4 ----
#pragma unroll
        for (int i = 0; i < 8; i++) {
            int idx  = tid + i * 256;
            int row  = idx >> 4;               // 0..127
            int col4 = (idx & 15) * 4;         // 0..60 within chunk
            float4 v = make_float4(0.f, 0.f, 0.f, 0.f);
            if (row0 + row < M) {
                v = *(const float4*)(A + (size_t)(row0 + row) * 128 + kc + col4);
                if (FUSE) {
                    float4 bb = *(const float4*)(bias + kc + col4);
                    v.x = fmaxf(v.x + bb.x, 0.0f);
                    v.y = fmaxf(v.y + bb.y, 0.0f);
                    v.z = fmaxf(v.z + bb.z, 0.0f);
                    v.w = fmaxf(v.w + bb.w, 0.0f);
                }
            }
            uint32_t h01, l01, h23, l23;
            split_pack(v.x, v.y, h01, l01);
            split_pack(v.z, v.w, h23, l23);
            uint32_t off = row * ASTR + col4 * 2;
            *(uint2*)(smem + off)       = make_uint2(h01, h23);
            *(uint2*)(smem + ASZ + off) = make_uint2(l01, l23);
        }

        // ---- W chunk: copy pre-split bf16 into padded smem ----
        {
            constexpr int ROWB = BN * 2;       // data bytes per k-row
            constexpr int VPR  = ROWB / 16;    // uint4 per row
            for (int u = tid; u < 2 * KC * VPR; u += 256) {
                int t = u / (KC * VPR);        // 0 = hi, 1 = lo
                int v2 = u % (KC * VPR);
                int r = v2 / VPR;
                int o = (v2 % VPR) * 16;
                const char* src = (const char*)(t ? Wlo : Whi) + (kc + r) * ROWB + o;
                char* dst = smem + (2 * ASZ + t * BSZ) + r * BSTR + o;
                *(uint4*)dst = *(const uint4*)src;
            }
        }
        __syncthreads();

        // ---- 3-term HMMA sweep over this chunk ----
#pragma unroll
        for (int term = 0; term < 3; term++) {
            uint32_t At = (term == 2) ? pAlo : pAhi;
            uint32_t Bt = (term == 1) ? pBlo : pBhi;
#pragma unroll
            for (int kb = 0; kb < KC; kb += 16) {
                uint32_t a[2][4];
#pragma unroll
                for (int mi = 0; mi < 2; mi++)
                    ldsm_x4(a[mi], At + (uint32_t)(wm * 32 + mi * 16 + r8) * ASTR
                                      + (kb + c8) * 2);
                uint32_t b[NB][4];
#pragma unroll
                for (int nb = 0; nb < NB; nb++)
                    ldsm_x4_t(b[nb], Bt + (uint32_t)(kb + r8) * BSTR
                                        + (wn * NW + nb * 16 + c8) * 2);
#pragma unroll
                for (int mi = 0; mi < 2; mi++)
#pragma unroll
                    for (int nf = 0; nf < NF; nf++)
                        mma_bf16(d[mi][nf], a[mi], &b[nf >> 1][(nf & 1) * 2]);
            }
        }
        __syncthreads();
    }

    // ---- epilogue: D regs -> global ----
    const int g   = lane >> 2;
    const int tig = lane & 3;
#pragma unroll
    for (int mi = 0; mi < 2; mi++) {
        int r1 = row0 + wm * 32 + mi * 16 + g;
#pragma unroll
        for (int nf = 0; nf < NF; nf++) {
            int col = wn * NW + nf * 8 + tig * 2;
            if (r1 < M)
                *(float2*)(H + (size_t)r1 * BN + col) =
                    make_float2(d[mi][nf][0], d[mi][nf][1]);
            if (r1 + 8 < M)
                *(float2*)(H + (size_t)(r1 + 8) * BN + col) =
                    make_float2(d[mi][nf][2], d[mi][nf][3]);
        }
    }
}

// ---------------------------------------------------------------------------
// launch
// ---------------------------------------------------------------------------
extern "C" void kernel_launch(void* const* d_in, const int* in_sizes, int n_in,
                              void* d_out, int out_size) {
    const float* x  = (const float*)d_in[0];
    const int*   ei = (const int*)  d_in[1];
    const float* W1 = (const float*)d_in[2];
    const float* b1 = (const float*)d_in[3];
    const float* W2 = (const float*)d_in[4];
    const float* b2 = (const float*)d_in[5];
    float* out = (float*)d_out;

    const int N = in_sizes[0] / F_IN;
    const int E = in_sizes[1] / 2;

    float *p_h1, *p_agg, *p_h3;
    cudaGetSymbolAddress((void**)&p_h1,  g_h1);
    cudaGetSymbolAddress((void**)&p_agg, g_agg);
    cudaGetSymbolAddress((void**)&p_h3,  g_h3);
    __nv_bfloat16 *p_w1h, *p_w1l, *p_w2h, *p_w2l;
    cudaGetSymbolAddress((void**)&p_w1h, g_w1hi);
    cudaGetSymbolAddress((void**)&p_w1l, g_w1lo);
    cudaGetSymbolAddress((void**)&p_w2h, g_w2hi);
    cudaGetSymbolAddress((void**)&p_w2l, g_w2lo);

    const int T = 256;
    const int nScanBlocks = (N + 1023) / 1024;

    // smem: 2 A tiles (18432 each) + 2 W tiles (KC=64 rows)
    const int smem1 = 2 * 18432 + 2 * 64 * (128 * 2 + 16);  // 71,680
    const int smem2 = 2 * 18432 + 2 * 64 * (64 * 2 + 16);   // 55,296
    cudaFuncSetAttribute(k_gemm_mma<128, false>,
                         cudaFuncAttributeMaxDynamicSharedMemorySize, smem1);
    cudaFuncSetAttribute(k_gemm_mma<64, true>,
                         cudaFuncAttributeMaxDynamicSharedMemorySize, smem2);

    // ---- degrees -> (dinv fused) -> CSR ----
    k_deg_zero  <<<(N + T - 1) / T, T>>>(N);
    k_deg_count <<<(E + T - 1) / T, T>>>(ei, E);
    k_scan_local<<<nScanBlocks, 1024>>>(N);
    k_scan_bsums<<<1, 32>>>(nScanBlocks);
    k_scan_add  <<<nScanBlocks, 1024>>>(N, E);
    k_fill      <<<(E + T - 1) / T, T>>>(ei, E);

    // ---- weight prep ----
    k_prep_w<<<(128 * 128 + 128 * 64 + T - 1) / T, T>>>(W1, W2);

    // ---- layer 1: HMMA GEMM -> gather ----
    k_gemm_mma<128, false><<<(N + 127) / 128, 256, smem1>>>(x, p_w1h, p_w1l,
                                                            nullptr, p_h1, N);
    k_gather<F_HID, false><<<(N + 7) / 8, 256>>>(p_h1, nullptr, p_agg, N);

    // ---- layer 2: HMMA GEMM (fused relu(agg+b1)) -> gather (fused relu+b2) ----
    k_gemm_mma<64, true><<<(N + 127) / 128, 256, smem2>>>(p_agg, p_w2h, p_w2l,
                                                          b1, p_h3, N);
    k_gather<F_OUT, true><<<(N + 7) / 8, 256>>>(p_h3, b2, out, N);
}